// round 4
// baseline (speedup 1.0000x reference)
#include <cuda_runtime.h>

// ce_loss_aux: masked binary one-hot cross-entropy, persistent fused kernel.
//
// 592 persistent blocks grid-stride over 512-pair chunks (1024 positions).
// Per chunk: fully-invalid -> skip; fully-valid -> 8 batched LDG.128 + 4 logs
// per thread; boundary -> predicated. Loop iterations are independent, so
// loads of the next chunk overlap compute of the current one.
// Last-arriving block does the deterministic final reduction.

#define NTHREADS 256
#define PPT 2                                   // float4-pairs per thread per chunk
#define CHUNK_PAIRS (NTHREADS * PPT)            // 512 pairs / chunk
#define NBLOCKS 592                             // 148 SMs * 4

__device__ float        g_partials[8192];
__device__ unsigned int g_counter;              // zero-init; reset by last block

__global__ __launch_bounds__(NTHREADS)
void ce_fused_kernel(const float* __restrict__ y_true,
                     const float* __restrict__ y_pred,
                     const int*   __restrict__ doc_len,
                     float* __restrict__ out,
                     int B, int L, int chunksPerRow, int totalChunks, int nBlocks)
{
    const int pairsPerRow = L >> 1;
    float acc = 0.0f;

    for (int c = blockIdx.x; c < totalChunks; c += nBlocks) {
        const int b     = c / chunksPerRow;
        const int chunk = c - b * chunksPerRow;
        const int d     = __ldg(&doc_len[b]);

        const int pairBase = chunk * CHUNK_PAIRS;
        const int lStart   = pairBase * 2;
        if (lStart >= d) continue;                       // fully invalid: no loads

        const float4* t4 = reinterpret_cast<const float4*>(y_true) + (size_t)b * pairsPerRow;
        const float4* p4 = reinterpret_cast<const float4*>(y_pred) + (size_t)b * pairsPerRow;

        if (lStart + CHUNK_PAIRS * 2 <= d) {
            // ---- fully valid: batched loads, then compute ----
            float4 t[PPT], p[PPT];
            #pragma unroll
            for (int i = 0; i < PPT; i++)
                t[i] = __ldg(&t4[pairBase + i * NTHREADS + threadIdx.x]);
            #pragma unroll
            for (int i = 0; i < PPT; i++)
                p[i] = __ldg(&p4[pairBase + i * NTHREADS + threadIdx.x]);
            #pragma unroll
            for (int i = 0; i < PPT; i++) {
                float s0 = (t[i].y == 1.0f) ? p[i].y : p[i].x;   // one-hot select
                float s1 = (t[i].w == 1.0f) ? p[i].w : p[i].z;
                acc -= __logf(s0 * s1);        // product in (1e-8, 1): safe fp32
            }
        } else {
            // ---- boundary chunk: per-pair predication on d ----
            #pragma unroll
            for (int i = 0; i < PPT; i++) {
                int pr = pairBase + i * NTHREADS + threadIdx.x;
                int l0 = pr << 1;
                if (l0 < d) {
                    float4 t = __ldg(&t4[pr]);
                    float4 p = __ldg(&p4[pr]);
                    float s0 = (t.y == 1.0f) ? p.y : p.x;
                    acc -= __logf(s0);
                    if (l0 + 1 < d) {
                        float s1 = (t.w == 1.0f) ? p.w : p.z;
                        acc -= __logf(s1);
                    }
                }
            }
        }
    }

    // ---- block reduction ----
    __shared__ float red[NTHREADS / 32];
    #pragma unroll
    for (int o = 16; o > 0; o >>= 1)
        acc += __shfl_down_sync(0xFFFFFFFFu, acc, o);
    if ((threadIdx.x & 31) == 0) red[threadIdx.x >> 5] = acc;
    __syncthreads();
    if (threadIdx.x < 32) {
        float v = (threadIdx.x < NTHREADS / 32) ? red[threadIdx.x] : 0.0f;
        #pragma unroll
        for (int o = 4; o > 0; o >>= 1)
            v += __shfl_down_sync(0xFFFFFFFFu, v, o);
        if (threadIdx.x == 0) g_partials[blockIdx.x] = v;
    }

    // ---- last-block final reduction (deterministic fixed-order sums) ----
    __shared__ bool amLast;
    if (threadIdx.x == 0) {
        __threadfence();
        unsigned int prev = atomicAdd(&g_counter, 1u);
        amLast = (prev == (unsigned int)(nBlocks - 1));
    }
    __syncthreads();

    if (amLast) {
        float ls = 0.0f;
        for (int i = threadIdx.x; i < nBlocks; i += NTHREADS)
            ls += g_partials[i];
        float ln = 0.0f;
        for (int i = threadIdx.x; i < B; i += NTHREADS)
            ln += (float)__ldg(&doc_len[i]);

        #pragma unroll
        for (int o = 16; o > 0; o >>= 1) {
            ls += __shfl_down_sync(0xFFFFFFFFu, ls, o);
            ln += __shfl_down_sync(0xFFFFFFFFu, ln, o);
        }
        __shared__ float rl[NTHREADS / 32], rn[NTHREADS / 32];
        if ((threadIdx.x & 31) == 0) {
            rl[threadIdx.x >> 5] = ls;
            rn[threadIdx.x >> 5] = ln;
        }
        __syncthreads();
        if (threadIdx.x == 0) {
            float sumL = 0.0f, sumN = 0.0f;
            #pragma unroll
            for (int i = 0; i < NTHREADS / 32; i++) { sumL += rl[i]; sumN += rn[i]; }
            out[0] = sumL / sumN;
            g_counter = 0;                      // reset for next graph replay
        }
    }
}

extern "C" void kernel_launch(void* const* d_in, const int* in_sizes, int n_in,
                              void* d_out, int out_size)
{
    const float* y_true  = (const float*)d_in[0];
    const float* y_pred  = (const float*)d_in[1];
    const int*   doc_len = (const int*)d_in[2];
    float*       out     = (float*)d_out;

    int B = in_sizes[2];
    int L = in_sizes[0] / (2 * B);

    int pairsPerRow  = L >> 1;
    int chunksPerRow = (pairsPerRow + CHUNK_PAIRS - 1) / CHUNK_PAIRS;
    int totalChunks  = B * chunksPerRow;
    int nBlocks      = NBLOCKS < totalChunks ? NBLOCKS : totalChunks;

    ce_fused_kernel<<<nBlocks, NTHREADS>>>(y_true, y_pred, doc_len, out,
                                           B, L, chunksPerRow, totalChunks, nBlocks);
}

// round 5
// speedup vs baseline: 1.0049x; 1.0049x over previous
#include <cuda_runtime.h>

// ce_loss_aux: masked binary one-hot cross-entropy, fused single kernel.
//
// One block per (row, 1024-pair chunk) -> 2048 blocks.
// __launch_bounds__(256, 4) raises the reg budget to 64 so the 8 float4
// loads per thread stay front-batched (16 cache lines in flight per warp).
// Last-arriving block does the deterministic final reduction.

#define NTHREADS 256
#define PPT 4                                   // float4-pairs per thread
#define CHUNK_PAIRS (NTHREADS * PPT)            // 1024 pairs / block

__device__ float        g_partials[8192];
__device__ unsigned int g_counter;              // zero-init; reset by last block

__global__ __launch_bounds__(NTHREADS, 4)
void ce_fused_kernel(const float* __restrict__ y_true,
                     const float* __restrict__ y_pred,
                     const int*   __restrict__ doc_len,
                     float* __restrict__ out,
                     int B, int L, int chunksPerRow, int nBlocks)
{
    const int b     = blockIdx.x / chunksPerRow;
    const int chunk = blockIdx.x - b * chunksPerRow;
    const int d     = __ldg(&doc_len[b]);

    const int pairBase = chunk * CHUNK_PAIRS;
    const int lStart   = pairBase * 2;

    float acc = 0.0f;

    if (lStart < d) {
        const float4* t4 = reinterpret_cast<const float4*>(y_true) + (size_t)b * (L >> 1);
        const float4* p4 = reinterpret_cast<const float4*>(y_pred) + (size_t)b * (L >> 1);

        if (lStart + CHUNK_PAIRS * 2 <= d) {
            // ---- fully valid: front-batch ALL 8 LDG.128, then compute ----
            float4 t[PPT], p[PPT];
            #pragma unroll
            for (int i = 0; i < PPT; i++)
                t[i] = __ldg(&t4[pairBase + i * NTHREADS + threadIdx.x]);
            #pragma unroll
            for (int i = 0; i < PPT; i++)
                p[i] = __ldg(&p4[pairBase + i * NTHREADS + threadIdx.x]);

            #pragma unroll
            for (int i = 0; i < PPT; i++) {
                float s0 = (t[i].y == 1.0f) ? p[i].y : p[i].x;   // one-hot select
                float s1 = (t[i].w == 1.0f) ? p[i].w : p[i].z;
                acc -= __logf(s0 * s1);        // product in (1e-8, 1): safe fp32
            }
        } else {
            // ---- boundary chunk: per-pair predication on d ----
            #pragma unroll
            for (int i = 0; i < PPT; i++) {
                int pr = pairBase + i * NTHREADS + threadIdx.x;
                int l0 = pr << 1;
                if (l0 < d) {
                    float4 t = __ldg(&t4[pr]);
                    float4 p = __ldg(&p4[pr]);
                    float s0 = (t.y == 1.0f) ? p.y : p.x;
                    acc -= __logf(s0);
                    if (l0 + 1 < d) {
                        float s1 = (t.w == 1.0f) ? p.w : p.z;
                        acc -= __logf(s1);
                    }
                }
            }
        }
    }

    // ---- block reduction ----
    __shared__ float red[NTHREADS / 32];
    #pragma unroll
    for (int o = 16; o > 0; o >>= 1)
        acc += __shfl_down_sync(0xFFFFFFFFu, acc, o);
    if ((threadIdx.x & 31) == 0) red[threadIdx.x >> 5] = acc;
    __syncthreads();
    if (threadIdx.x < 32) {
        float v = (threadIdx.x < NTHREADS / 32) ? red[threadIdx.x] : 0.0f;
        #pragma unroll
        for (int o = 4; o > 0; o >>= 1)
            v += __shfl_down_sync(0xFFFFFFFFu, v, o);
        if (threadIdx.x == 0) g_partials[blockIdx.x] = v;
    }

    // ---- last-block final reduction (deterministic fixed-order sums) ----
    __shared__ bool amLast;
    if (threadIdx.x == 0) {
        __threadfence();
        unsigned int prev = atomicAdd(&g_counter, 1u);
        amLast = (prev == (unsigned int)(nBlocks - 1));
    }
    __syncthreads();

    if (amLast) {
        float ls = 0.0f;
        for (int i = threadIdx.x; i < nBlocks; i += NTHREADS)
            ls += g_partials[i];
        float ln = 0.0f;
        for (int i = threadIdx.x; i < B; i += NTHREADS)
            ln += (float)__ldg(&doc_len[i]);

        #pragma unroll
        for (int o = 16; o > 0; o >>= 1) {
            ls += __shfl_down_sync(0xFFFFFFFFu, ls, o);
            ln += __shfl_down_sync(0xFFFFFFFFu, ln, o);
        }
        __shared__ float rl[NTHREADS / 32], rn[NTHREADS / 32];
        if ((threadIdx.x & 31) == 0) {
            rl[threadIdx.x >> 5] = ls;
            rn[threadIdx.x >> 5] = ln;
        }
        __syncthreads();
        if (threadIdx.x == 0) {
            float sumL = 0.0f, sumN = 0.0f;
            #pragma unroll
            for (int i = 0; i < NTHREADS / 32; i++) { sumL += rl[i]; sumN += rn[i]; }
            out[0] = sumL / sumN;
            g_counter = 0;                      // reset for next graph replay
        }
    }
}

extern "C" void kernel_launch(void* const* d_in, const int* in_sizes, int n_in,
                              void* d_out, int out_size)
{
    const float* y_true  = (const float*)d_in[0];
    const float* y_pred  = (const float*)d_in[1];
    const int*   doc_len = (const int*)d_in[2];
    float*       out     = (float*)d_out;

    int B = in_sizes[2];
    int L = in_sizes[0] / (2 * B);

    int pairsPerRow  = L >> 1;
    int chunksPerRow = (pairsPerRow + CHUNK_PAIRS - 1) / CHUNK_PAIRS;
    int nBlocks      = B * chunksPerRow;

    ce_fused_kernel<<<nBlocks, NTHREADS>>>(y_true, y_pred, doc_len, out,
                                           B, L, chunksPerRow, nBlocks);
}